// round 4
// baseline (speedup 1.0000x reference)
#include <cuda_runtime.h>

// out[b, f] = x0[b, f] * dot(x[b,:], w) + bias[f] + x[b, f]
// B = 16384 rows, F = 2048 cols, fp32.
//
// R4: persistent grid (152 SMs x 4 CTAs, one wave) with a software-pipelined
// grid-stride row loop:
//  - next row's x / x0 loads issue BEFORE the barrier -> DRAM requests stay
//    in flight across the reduce, no per-row cold start, no wave transitions.
//  - w held in registers across all rows (out of the hot loop entirely).
//  - warp_sums ping-pong on loop parity -> single __syncthreads per row.
//  - default cache policy (R3 showed __ldcs/__stcs regress).

#define F_DIM 2048
#define VEC_PER_ROW (F_DIM / 4)   // 512 float4
#define THREADS 256
#define NWARPS (THREADS / 32)
#define GRID (152 * 4)

__global__ __launch_bounds__(THREADS, 4)
void cross_persistent_kernel(const float4* __restrict__ x0,
                             const float4* __restrict__ x,
                             const float4* __restrict__ w,
                             const float4* __restrict__ bias,
                             float4* __restrict__ out,
                             int B)
{
    const int tid  = threadIdx.x;
    const int i0   = tid;
    const int i1   = tid + THREADS;
    const int lane = tid & 31;
    const int warp = tid >> 5;
    const int stride = gridDim.x;

    __shared__ float warp_sums[2][NWARPS];

    // Loop-invariant: weights live in registers for every row this CTA does.
    const float4 wa = w[i0];
    const float4 wb = w[i1];

    int row = blockIdx.x;
    if (row >= B) return;

    long base = (long)row * VEC_PER_ROW;
    float4 xa  = x[base + i0];
    float4 xb  = x[base + i1];
    float4 x0a = x0[base + i0];
    float4 x0b = x0[base + i1];

    int parity = 0;
    for (;;) {
        const int  next     = row + stride;
        const bool has_next = next < B;
        const long nbase    = (long)next * VEC_PER_ROW;

        // Per-thread partial dot on the current row.
        float s = xa.x * wa.x + xa.y * wa.y + xa.z * wa.z + xa.w * wa.w
                + xb.x * wb.x + xb.y * wb.y + xb.z * wb.z + xb.w * wb.w;

        // bias reload each row (L1-hit, keeps register count down) and
        // precompute (bias + x) before the barrier.
        const float4 ba = bias[i0];
        const float4 bb = bias[i1];
        float4 pa, pb;
        pa.x = ba.x + xa.x;  pa.y = ba.y + xa.y;
        pa.z = ba.z + xa.z;  pa.w = ba.w + xa.w;
        pb.x = bb.x + xb.x;  pb.y = bb.y + xb.y;
        pb.z = bb.z + xb.z;  pb.w = bb.w + xb.w;

        // Warp reduce.
        #pragma unroll
        for (int off = 16; off > 0; off >>= 1)
            s += __shfl_xor_sync(0xFFFFFFFFu, s, off);
        if (lane == 0) warp_sums[parity][warp] = s;

        // Prefetch next row BEFORE the barrier: these LDGs fly during the
        // reduce + epilogue, hiding the DRAM round-trip entirely.
        float4 nxa, nxb, nx0a, nx0b;
        if (has_next) {
            nxa  = x[nbase + i0];
            nxb  = x[nbase + i1];
            nx0a = x0[nbase + i0];
            nx0b = x0[nbase + i1];
        }

        __syncthreads();

        float xw = 0.0f;
        #pragma unroll
        for (int i = 0; i < NWARPS; i++)
            xw += warp_sums[parity][i];   // broadcast LDS

        // out = x0 * xw + (bias + x)
        float4 oa, ob;
        oa.x = fmaf(x0a.x, xw, pa.x);
        oa.y = fmaf(x0a.y, xw, pa.y);
        oa.z = fmaf(x0a.z, xw, pa.z);
        oa.w = fmaf(x0a.w, xw, pa.w);
        ob.x = fmaf(x0b.x, xw, pb.x);
        ob.y = fmaf(x0b.y, xw, pb.y);
        ob.z = fmaf(x0b.z, xw, pb.z);
        ob.w = fmaf(x0b.w, xw, pb.w);

        out[base + i0] = oa;
        out[base + i1] = ob;

        if (!has_next) break;
        row  = next;
        base = nbase;
        xa = nxa;  xb = nxb;  x0a = nx0a;  x0b = nx0b;
        parity ^= 1;   // ping-pong warp_sums; no second barrier needed
    }
}

extern "C" void kernel_launch(void* const* d_in, const int* in_sizes, int n_in,
                              void* d_out, int out_size)
{
    const float4* x0   = (const float4*)d_in[0];
    const float4* x    = (const float4*)d_in[1];
    const float4* w    = (const float4*)d_in[2];
    const float4* bias = (const float4*)d_in[3];
    float4* out = (float4*)d_out;

    const int rows = in_sizes[0] / F_DIM;  // 16384
    const int grid = (GRID < rows) ? GRID : rows;
    cross_persistent_kernel<<<grid, THREADS>>>(x0, x, w, bias, out, rows);
}

// round 5
// speedup vs baseline: 1.0372x; 1.0372x over previous
#include <cuda_runtime.h>

// out[b, f] = x0[b, f] * dot(x[b,:], w) + bias[f] + x[b, f]
// B = 16384 rows, F = 2048 cols, fp32.
//
// R5: R2 structure (front-batched loads, single barrier, default cache
// policy) but 512 threads/CTA, one float4 per stream per thread:
//  - regs ~26 -> full occupancy (2048 thr/SM) while keeping the 4-deep
//    front-batch of LDG.128s.
//  - each warp-instruction covers a dense contiguous 4KB span per stream.

#define F_DIM 2048
#define VEC_PER_ROW (F_DIM / 4)   // 512 float4
#define THREADS 512
#define NWARPS (THREADS / 32)     // 16

__global__ __launch_bounds__(THREADS)
void cross_fused_kernel(const float4* __restrict__ x0,
                        const float4* __restrict__ x,
                        const float4* __restrict__ w,
                        const float4* __restrict__ bias,
                        float4* __restrict__ out)
{
    const int row = blockIdx.x;
    const int tid = threadIdx.x;
    const long idx = (long)row * VEC_PER_ROW + tid;

    // Front-batched loads: 4 LDG.128 in flight per thread.
    float4 xa  = x[idx];
    float4 x0a = x0[idx];
    float4 wa  = w[tid];
    float4 ba  = bias[tid];

    // Per-thread partial dot.
    float s = xa.x * wa.x + xa.y * wa.y + xa.z * wa.z + xa.w * wa.w;

    // Precompute (bias + x) before the barrier.
    float4 pa;
    pa.x = ba.x + xa.x;  pa.y = ba.y + xa.y;
    pa.z = ba.z + xa.z;  pa.w = ba.w + xa.w;

    // Warp reduce.
    #pragma unroll
    for (int off = 16; off > 0; off >>= 1)
        s += __shfl_xor_sync(0xFFFFFFFFu, s, off);

    // Single-barrier cross-warp reduce: lane 0 publishes, everyone sums.
    __shared__ float warp_sums[NWARPS];
    const int lane = tid & 31;
    const int warp = tid >> 5;
    if (lane == 0) warp_sums[warp] = s;
    __syncthreads();

    float xw = 0.0f;
    #pragma unroll
    for (int i = 0; i < NWARPS; i++)
        xw += warp_sums[i];   // broadcast LDS, conflict-free

    // out = x0 * xw + (bias + x)
    float4 oa;
    oa.x = fmaf(x0a.x, xw, pa.x);
    oa.y = fmaf(x0a.y, xw, pa.y);
    oa.z = fmaf(x0a.z, xw, pa.z);
    oa.w = fmaf(x0a.w, xw, pa.w);

    out[idx] = oa;
}

extern "C" void kernel_launch(void* const* d_in, const int* in_sizes, int n_in,
                              void* d_out, int out_size)
{
    const float4* x0   = (const float4*)d_in[0];
    const float4* x    = (const float4*)d_in[1];
    const float4* w    = (const float4*)d_in[2];
    const float4* bias = (const float4*)d_in[3];
    float4* out = (float4*)d_out;

    const int rows = in_sizes[0] / F_DIM;  // 16384
    cross_fused_kernel<<<rows, THREADS>>>(x0, x, w, bias, out);
}